// round 3
// baseline (speedup 1.0000x reference)
#include <cuda_runtime.h>
#include <cstdint>
#include <cstddef>

#define DIM      900
#define TLEN     31000
#define DISCARD  1000
#define OUTCOLS  29999      /* TLEN - DISCARD - 1 */
#define NCTA     90
#define RPC      10         /* rows per CTA */
#define CWARPS   5          /* compute warps per CTA, 2 rows each */
#define NTHREADS 160        /* 5 warps */
#define PADDIM   1024       /* padded x length: 8 chunks of 128 */

// Ping-pong global state broadcast + monotonic arrival counter.
// Zero-initialized at module load. ctr only ever grows (90 arrivals per step,
// 90*TLEN per launch), so graph replays need no reset: each launch recovers
// its base by rounding the first read down to a multiple of NCTA.
__device__ __align__(16) float g_x[2][PADDIM];
__device__ unsigned long long g_ctr;

__device__ __forceinline__ unsigned long long ld_acq(const unsigned long long* p) {
    unsigned long long v;
    asm volatile("ld.acquire.gpu.global.b64 %0, [%1];" : "=l"(v) : "l"(p) : "memory");
    return v;
}
__device__ __forceinline__ void red_rel_add1(unsigned long long* p) {
    asm volatile("red.release.gpu.global.add.u64 [%0], 1;" :: "l"(p) : "memory");
}
__device__ __forceinline__ float4 ld_cg4(const float4* p) {
    float4 v;
    asm volatile("ld.global.cg.v4.f32 {%0,%1,%2,%3}, [%4];"
                 : "=f"(v.x), "=f"(v.y), "=f"(v.z), "=f"(v.w) : "l"(p) : "memory");
    return v;
}
__device__ __forceinline__ void st_cg2(float* p, float a, float b) {
    asm volatile("st.global.cg.v2.f32 [%0], {%1,%2};" :: "l"(p), "f"(a), "f"(b) : "memory");
}
__device__ __forceinline__ unsigned long long pk2(float a, float b) {
    unsigned long long r;
    asm("mov.b64 %0, {%1,%2};" : "=l"(r) : "f"(a), "f"(b));
    return r;
}
// Packed dual fp32 FMA (B300 FFMA2) — exact fp32 semantics, 2 MACs/instr.
__device__ __forceinline__ void fma2(unsigned long long& acc,
                                     unsigned long long a, unsigned long long b) {
    asm("fma.rn.f32x2 %0, %1, %2, %0;" : "+l"(acc) : "l"(a), "l"(b));
}
__device__ __forceinline__ float sum2(unsigned long long a) {
    float lo, hi;
    asm("mov.b64 {%0,%1}, %2;" : "=f"(lo), "=f"(hi) : "l"(a));
    return lo + hi;
}

__global__ void __launch_bounds__(NTHREADS, 1) esn_persistent(
    const float* __restrict__ W,     // (900, 900) row-major, symmetric
    const float* __restrict__ Win,   // (900, 900) row-major; column 0 used
    const float* __restrict__ u,     // (31000,)
    float* __restrict__ out)         // (900, 29999) row-major
{
    __shared__ __align__(16) float x_sm[PADDIM];
    __shared__ unsigned long long s_base;

    const int tid  = threadIdx.x;
    const int cta  = blockIdx.x;
    const int warp = tid >> 5;
    const int lane = tid & 31;

    // Zero x_sm once; pad region [900,1024) stays zero forever (stage writes <900).
    for (int i = tid; i < PADDIM; i += NTHREADS) x_sm[i] = 0.0f;

    // Launch base: round the counter down to a multiple of NCTA. Before any CTA
    // posts its step-0 arrival it has already read the counter, and no CTA can
    // post a step-1 arrival until all 90 step-0 arrivals exist -> any read here
    // sees base + k with 0 <= k <= 89. base is always a multiple of 90.
    if (tid == 0) {
        unsigned long long o = ld_acq(&g_ctr);
        s_base = o - (o % (unsigned long long)NCTA);
    }

    // ---- Load this warp's 2 rows of W into registers, pre-scaled by 0.9 ----
    unsigned long long w0p[8][2], w1p[8][2];
    const int r0 = cta * RPC + warp * 2;
    #pragma unroll
    for (int k = 0; k < 8; ++k) {
        const int col = k * 128 + lane * 4;
        float a0 = 0.f, a1 = 0.f, a2 = 0.f, a3 = 0.f;
        float b0 = 0.f, b1 = 0.f, b2 = 0.f, b3 = 0.f;
        if (col + 3 < DIM) {
            float4 va = *(const float4*)(W + (size_t)r0 * DIM + col);
            float4 vb = *(const float4*)(W + (size_t)(r0 + 1) * DIM + col);
            a0 = va.x; a1 = va.y; a2 = va.z; a3 = va.w;
            b0 = vb.x; b1 = vb.y; b2 = vb.z; b3 = vb.w;
        }
        const float sr = 0.9f;  // reference: w_eff = 0.9*W elementwise
        w0p[k][0] = pk2(sr * a0, sr * a1);
        w0p[k][1] = pk2(sr * a2, sr * a3);
        w1p[k][0] = pk2(sr * b0, sr * b1);
        w1p[k][1] = pk2(sr * b2, sr * b3);
    }
    const float winA = Win[(size_t)r0 * DIM];          // W_in[r0, 0]
    const float winB = Win[(size_t)(r0 + 1) * DIM];    // W_in[r0+1, 0]

    __syncthreads();
    const unsigned long long base = s_base;

    // lane 0 tracks row r0's state, lane 16 tracks row r0+1's; others junk.
    float xold = 0.0f;

    for (int s = 0; s < TLEN; ++s) {
        const float u_s = __ldg(u + s);   // prefetch, overlaps the spin

        if (s > 0) {
            // --- bar1: wait until all 90 CTAs published step s-1 ---
            if (tid == 0) {
                const unsigned long long tgt =
                    base + (unsigned long long)NCTA * (unsigned long long)s;
                while (ld_acq(&g_ctr) < tgt) { }
            }
            __syncthreads();
            // --- stage x_{s-1}: 225 float4 over 160 threads (L2 -> smem) ---
            const float4* src = (const float4*)g_x[(s - 1) & 1];
            for (int i = tid; i < DIM / 4; i += NTHREADS)
                *(float4*)(x_sm + i * 4) = ld_cg4(src + i);
            __syncthreads();   // bar2
        }

        // ---- compute this warp's 2 rows ----
        float sA = 0.0f, sB = 0.0f;
        if (s > 0) {
            unsigned long long a0 = 0, a1 = 0, a2 = 0, a3 = 0;
            #pragma unroll
            for (int k = 0; k < 8; ++k) {
                ulonglong2 xv = *(const ulonglong2*)(x_sm + k * 128 + lane * 4);
                fma2(a0, w0p[k][0], xv.x);
                fma2(a1, w0p[k][1], xv.y);
                fma2(a2, w1p[k][0], xv.x);
                fma2(a3, w1p[k][1], xv.y);
            }
            sA = sum2(a0) + sum2(a1);
            sB = sum2(a2) + sum2(a3);
            #pragma unroll
            for (int off = 16; off > 0; off >>= 1) {
                sA += __shfl_xor_sync(0xffffffffu, sA, off);
                sB += __shfl_xor_sync(0xffffffffu, sB, off);
            }
        }
        // lane 0 -> row r0, lane 16 -> row r0+1 (all lanes compute, no branches)
        const float accv = (lane == 16) ? sB : sA;
        const float wv   = (lane == 16) ? winB : winA;
        const float xn   = 0.3f * xold + 0.7f * tanhf(accv + wv * u_s);
        xold = xn;

        const float xn0 = __shfl_sync(0xffffffffu, xn, 0);
        const float xn1 = __shfl_sync(0xffffffffu, xn, 16);
        if (lane == 0) st_cg2(&g_x[s & 1][r0], xn0, xn1);   // publish x_s rows

        __syncthreads();   // bar3: all warps' data stores precede the release
        if (tid == 0) red_rel_add1(&g_ctr);   // release-arrive (fire & forget)

        // Output stores AFTER the release — off the inter-CTA critical path.
        if (s > DISCARD) {
            const int t = s - (DISCARD + 1);
            if (lane == 0)  out[(size_t)r0 * OUTCOLS + t]       = xn0;
            if (lane == 16) out[(size_t)(r0 + 1) * OUTCOLS + t] = xn1;
        }
    }
}

extern "C" void kernel_launch(void* const* d_in, const int* in_sizes, int n_in,
                              void* d_out, int out_size) {
    const float* W   = (const float*)d_in[0];
    const float* Win = (const float*)d_in[1];
    const float* u   = (const float*)d_in[2];
    esn_persistent<<<NCTA, NTHREADS>>>(W, Win, u, (float*)d_out);
}